// round 13
// baseline (speedup 1.0000x reference)
#include <cuda_runtime.h>
#include <cstdint>

#define NROW 512
#define HH 8
#define DD 32
#define INNER 256
#define ED 64
#define SCALE 0.17677669529663687f  // 1/sqrt(32)
#define ESTRIDE 68                  // padded row stride (floats), 16B-aligned rows
#define QSMEM (128 * ESTRIDE * 4)   // 34816 B dynamic smem (quarter row)
#define SPAD 132                    // sim_f row stride (floats), 16B-aligned
#define VPAD 130                    // v_sT row stride (8B-aligned, conflict-free)

// Scratch (device globals; no allocation in kernel_launch).
__device__ float g_q[NROW * INNER];
__device__ float g_k[NROW * INNER];
__device__ float g_v[NROW * INNER];
__device__ float g_t[NROW * HH * ED];        // [i][h][c]  t = We_h^T q_{h,i}
__device__ float g_qbe[NROW * HH];           // q_{h,i} . be_h
__device__ float g_simqk[HH * NROW * NROW];
__device__ float g_esim[HH * NROW * NROW];   // unnormalized exp*adj
__device__ float g_aggu[4 * NROW * HH * ED]; // [quarter][i][h][c] partial agg
__device__ float g_sump[4 * HH * NROW];      // [quarter][h][i] partial sums

typedef unsigned long long ull;

__device__ __forceinline__ ull fma2(ull a, ull b, ull c) {
    ull d;
    asm("fma.rn.f32x2 %0, %1, %2, %3;" : "=l"(d) : "l"(a), "l"(b), "l"(c));
    return d;
}
__device__ __forceinline__ ull pack2(float lo, float hi) {
    ull d;
    asm("mov.b64 %0, {%1, %2};" : "=l"(d) : "f"(lo), "f"(hi));
    return d;
}
__device__ __forceinline__ float2 unpack2(ull v) {
    float lo, hi;
    asm("mov.b64 {%0, %1}, %2;" : "=f"(lo), "=f"(hi) : "l"(v));
    return make_float2(lo, hi);
}
__device__ __forceinline__ float hsum2(ull v) {
    float2 f = unpack2(v);
    return f.x + f.y;
}
__device__ __forceinline__ void cp16(unsigned int daddr, const void* gptr) {
    asm volatile("cp.async.cg.shared.global [%0], [%1], 16;\n"
                 :: "r"(daddr), "l"(gptr));
}

// ---------------------------------------------------------------------------
// Kernel A: q/k/v projections + t = We_h^T q + qbe.  4 rows per block.
// ---------------------------------------------------------------------------
__global__ __launch_bounds__(256) void proj_kernel(
    const float* __restrict__ nodes,
    const float* __restrict__ Wq, const float* __restrict__ bq,
    const float* __restrict__ Wk, const float* __restrict__ bk,
    const float* __restrict__ Wv, const float* __restrict__ bv,
    const float* __restrict__ We, const float* __restrict__ be)
{
    __shared__ float node_s[4][128];
    __shared__ float q_s[4][INNER];
    const int t = threadIdx.x;
    const int i0 = blockIdx.x * 4;

    for (int idx = t; idx < 4 * 128; idx += 256)
        node_s[idx >> 7][idx & 127] = nodes[i0 * 128 + idx];
    __syncthreads();

    float aq[4], ak[4], av[4];
    const float bqv = bq[t], bkv = bk[t], bvv = bv[t];
#pragma unroll
    for (int r = 0; r < 4; r++) { aq[r] = bqv; ak[r] = bkv; av[r] = bvv; }

#pragma unroll 8
    for (int k = 0; k < 128; k++) {
        const float wq = Wq[k * INNER + t];
        const float wk = Wk[k * INNER + t];
        const float wv = Wv[k * INNER + t];
#pragma unroll
        for (int r = 0; r < 4; r++) {
            const float nv = node_s[r][k];
            aq[r] = fmaf(nv, wq, aq[r]);
            ak[r] = fmaf(nv, wk, ak[r]);
            av[r] = fmaf(nv, wv, av[r]);
        }
    }
#pragma unroll
    for (int r = 0; r < 4; r++) {
        g_q[(i0 + r) * INNER + t] = aq[r];
        g_k[(i0 + r) * INNER + t] = ak[r];
        g_v[(i0 + r) * INNER + t] = av[r];
        q_s[r][t] = aq[r];
    }
    __syncthreads();

    // t[i][h][c] = sum_d We[c, h*32+d] * q[i, h*32+d]
    for (int idx = t; idx < HH * ED; idx += 256) {
        const int h = idx >> 6, c = idx & 63;
        float acc[4] = {0.f, 0.f, 0.f, 0.f};
        const float* wrow = We + c * INNER + h * DD;
#pragma unroll
        for (int d = 0; d < DD; d++) {
            const float w = wrow[d];
#pragma unroll
            for (int r = 0; r < 4; r++)
                acc[r] = fmaf(w, q_s[r][h * DD + d], acc[r]);
        }
#pragma unroll
        for (int r = 0; r < 4; r++)
            g_t[(i0 + r) * (HH * ED) + idx] = acc[r];
    }

    if (t < 4 * HH) {
        const int r = t >> 3, h = t & 7;
        float s = 0.f;
#pragma unroll
        for (int d = 0; d < DD; d++)
            s = fmaf(q_s[r][h * DD + d], be[h * DD + d], s);
        g_qbe[(i0 + r) * HH + h] = s;
    }
}

// ---------------------------------------------------------------------------
// Kernel QK: simqk[h][i][j] = (q_h[i].k_h[j] + qbe[i][h]) * SCALE
// ---------------------------------------------------------------------------
__global__ __launch_bounds__(256) void qk_kernel()
{
    __shared__ float q_s[32][33];
    __shared__ float k_s[32][33];
    const int t = threadIdx.x;
    const int j0 = blockIdx.x * 32;
    const int i0 = blockIdx.y * 32;
    const int h  = blockIdx.z;

    {
        const int r = t >> 3, c4 = (t & 7) * 4;
        const float4 qv = *(const float4*)&g_q[(i0 + r) * INNER + h * DD + c4];
        q_s[r][c4 + 0] = qv.x; q_s[r][c4 + 1] = qv.y;
        q_s[r][c4 + 2] = qv.z; q_s[r][c4 + 3] = qv.w;
        const float4 kv = *(const float4*)&g_k[(j0 + r) * INNER + h * DD + c4];
        k_s[r][c4 + 0] = kv.x; k_s[r][c4 + 1] = kv.y;
        k_s[r][c4 + 2] = kv.z; k_s[r][c4 + 3] = kv.w;
    }
    __syncthreads();

    const int tx = t & 31, ty = t >> 5;
    float acc[4] = {0.f, 0.f, 0.f, 0.f};
#pragma unroll
    for (int d = 0; d < 32; d++) {
        const float kv = k_s[tx][d];
#pragma unroll
        for (int m = 0; m < 4; m++)
            acc[m] = fmaf(q_s[ty + m * 8][d], kv, acc[m]);
    }
#pragma unroll
    for (int m = 0; m < 4; m++) {
        const int i = i0 + ty + m * 8;
        g_simqk[((size_t)h * NROW + i) * NROW + j0 + tx] =
            (acc[m] + g_qbe[i * HH + h]) * SCALE;
    }
}

// ---------------------------------------------------------------------------
// Kernel B: quarter-row sim + exp + partial sums + partial unnormalized agg.
// grid 2048 = (row i) x (quarter), 256 threads, occ 3+ for latency overlap.
// Pass 1: thread = (head-group, j), 4 heads each. Pass 2: (jg, c4), 8 heads
// in registers. Partials combined later in outv (normalization is linear).
// ---------------------------------------------------------------------------
__global__ __launch_bounds__(256, 3) void simagg_kernel(
    const float* __restrict__ edges, const int* __restrict__ adj)
{
    extern __shared__ __align__(16) float e_s[];        // [128][ESTRIDE]
    __shared__ __align__(16) float t_s[HH * ESTRIDE];
    __shared__ __align__(16) float sim_f[HH * SPAD];    // [h][j] esim
    __shared__ float wsum[8 * 4];                       // [warp][4 heads]

    const int t = threadIdx.x;
    const int i = blockIdx.x >> 2;
    const int q = blockIdx.x & 3;
    const int jbase = q * 128;

    // ---- DMA: group A = c4 0..7 (floats 0..31), group B = c4 8..15 ----
    {
        const float* gsrc = edges + ((size_t)i * NROW + jbase) * ED;
        unsigned int sbase = (unsigned int)__cvta_generic_to_shared(e_s);
#pragma unroll
        for (int it = 0; it < 4; it++) {
            const int idx = t + it * 256;             // 1024: row=idx>>3, c4=idx&7
            const int row = idx >> 3, c4 = idx & 7;
            cp16(sbase + (unsigned int)(row * ESTRIDE + c4 * 4) * 4,
                 gsrc + (size_t)row * ED + c4 * 4);
        }
        asm volatile("cp.async.commit_group;\n" ::: "memory");
#pragma unroll
        for (int it = 0; it < 4; it++) {
            const int idx = t + it * 256;
            const int row = idx >> 3, c4 = (idx & 7) + 8;
            cp16(sbase + (unsigned int)(row * ESTRIDE + c4 * 4) * 4,
                 gsrc + (size_t)row * ED + c4 * 4);
        }
        asm volatile("cp.async.commit_group;\n" ::: "memory");
    }

    // ---- overlap DMA with staging ----
#pragma unroll
    for (int k = 0; k < 2; k++) {
        const int idx = t + k * 256;
        t_s[(idx >> 6) * ESTRIDE + (idx & 63)] = g_t[i * (HH * ED) + idx];
    }
    const int jj  = t & 127;
    const int hp4 = (t >> 7) * 4;      // heads hp4..hp4+3
    const int av = adj[i * NROW + jbase + jj];
    float sq[4];
#pragma unroll
    for (int hh = 0; hh < 4; hh++)
        sq[hh] = g_simqk[((size_t)(hp4 + hh) * NROW + i) * NROW + jbase + jj];

    // ---- pass 1: thread = (hp4, jj); 4 heads, dot over 64 c ----
    ull acc[4];
#pragma unroll
    for (int hh = 0; hh < 4; hh++) acc[hh] = 0ull;
    const longlong2* ep = (const longlong2*)&e_s[jj * ESTRIDE];

    asm volatile("cp.async.wait_group 1;\n" ::: "memory");
    __syncthreads();
    {
        longlong2 er[8];
#pragma unroll
        for (int u = 0; u < 8; u++) er[u] = ep[u];
#pragma unroll
        for (int hh = 0; hh < 4; hh++) {
            const longlong2* tp = (const longlong2*)&t_s[(hp4 + hh) * ESTRIDE];
            ull a = acc[hh];
#pragma unroll
            for (int u = 0; u < 8; u++) {
                const longlong2 tv = tp[u];
                a = fma2((ull)er[u].x, (ull)tv.x, a);
                a = fma2((ull)er[u].y, (ull)tv.y, a);
            }
            acc[hh] = a;
        }
    }
    asm volatile("cp.async.wait_group 0;\n" ::: "memory");
    __syncthreads();
    float ex[4];
    {
        longlong2 er[8];
#pragma unroll
        for (int u = 0; u < 8; u++) er[u] = ep[8 + u];
#pragma unroll
        for (int hh = 0; hh < 4; hh++) {
            const longlong2* tp = (const longlong2*)&t_s[(hp4 + hh) * ESTRIDE] + 8;
            ull a = acc[hh];
#pragma unroll
            for (int u = 0; u < 8; u++) {
                const longlong2 tv = tp[u];
                a = fma2((ull)er[u].x, (ull)tv.x, a);
                a = fma2((ull)er[u].y, (ull)tv.y, a);
            }
            const float simv = fmaf(hsum2(a), SCALE, sq[hh]);
            ex[hh] = av ? __expf(simv) : 0.f;
        }
    }

    // esim: smem (for pass 2) + gmem (for outv)
#pragma unroll
    for (int hh = 0; hh < 4; hh++) {
        sim_f[(hp4 + hh) * SPAD + jj] = ex[hh];
        g_esim[((size_t)(hp4 + hh) * NROW + i) * NROW + jbase + jj] = ex[hh];
    }

    // ---- partial sums over j ----
    {
        float s[4];
#pragma unroll
        for (int hh = 0; hh < 4; hh++) s[hh] = ex[hh];
#pragma unroll
        for (int o = 16; o > 0; o >>= 1)
#pragma unroll
            for (int hh = 0; hh < 4; hh++)
                s[hh] += __shfl_xor_sync(0xffffffffu, s[hh], o);
        if ((t & 31) == 0) {
            const int w = t >> 5;
#pragma unroll
            for (int hh = 0; hh < 4; hh++) wsum[w * 4 + hh] = s[hh];
        }
    }
    __syncthreads();
    if (t < HH) {
        // head t: warps 0..3 hold heads 0..3, warps 4..7 hold heads 4..7
        const int wbase = (t < 4) ? 0 : 4;
        const int hh = t & 3;
        float s = 0.f;
#pragma unroll
        for (int w = 0; w < 4; w++) s += wsum[(wbase + w) * 4 + hh];
        g_sump[q * (HH * NROW) + t * NROW + i] = s;
    }

    // ---- pass 2: thread = (jg 0..15, c4 0..15); 8 j per group ----
    ull pa[HH][2];
    const int jg = t >> 4;
    const int c4 = t & 15;
#pragma unroll
    for (int h = 0; h < HH; h++) { pa[h][0] = 0ull; pa[h][1] = 0ull; }
    {
        const int joff = jg * 8;
#pragma unroll
        for (int k4 = 0; k4 < 2; k4++) {
            float4 s4[HH];
#pragma unroll
            for (int h = 0; h < HH; h++)
                s4[h] = *(const float4*)&sim_f[h * SPAD + joff + k4 * 4];
#pragma unroll
            for (int kk = 0; kk < 4; kk++) {
                const int jx = joff + k4 * 4 + kk;
                const longlong2 e2 = *(const longlong2*)&e_s[jx * ESTRIDE + c4 * 4];
#pragma unroll
                for (int h = 0; h < HH; h++) {
                    const float sv = (kk == 0) ? s4[h].x : (kk == 1) ? s4[h].y
                                   : (kk == 2) ? s4[h].z : s4[h].w;
                    const ull sp = pack2(sv, sv);
                    pa[h][0] = fma2(sp, (ull)e2.x, pa[h][0]);
                    pa[h][1] = fma2(sp, (ull)e2.y, pa[h][1]);
                }
            }
        }
    }
    __syncthreads();                 // e_s reads done; alias for partials
    float4* part = (float4*)e_s;     // [jg][h][c4] float4 = 32 KB
#pragma unroll
    for (int h = 0; h < HH; h++) {
        const float2 A = unpack2(pa[h][0]);
        const float2 B = unpack2(pa[h][1]);
        part[(jg * 8 + h) * 16 + c4] = make_float4(A.x, A.y, B.x, B.y);
    }
    __syncthreads();
    if (t < 128) {                   // h = t>>4, c4m = t&15
        const int h = t >> 4;
        const int c4m = t & 15;
        float4 s = part[h * 16 + c4m];
#pragma unroll
        for (int g = 1; g < 16; g++) {
            const float4 p = part[(g * 8 + h) * 16 + c4m];
            s.x += p.x; s.y += p.y; s.z += p.z; s.w += p.w;
        }
        *(float4*)&g_aggu[((size_t)(q * NROW + i) * HH + h) * ED + c4m * 4] = s;
    }
}

// ---------------------------------------------------------------------------
// Kernel C: out = inv * (esim @ v + aggu @ We) + rs * be.
// grid (32 i-tiles of 16, 8 heads) = 256 blocks (2/SM), software-pipelined
// register prefetch of j-chunks. No atomics.
// ---------------------------------------------------------------------------
__global__ __launch_bounds__(256, 2) void outv_kernel(
    const float* __restrict__ We, const float* __restrict__ be,
    float* __restrict__ out)
{
    __shared__ float a_s[16 * 128];                   // esim tile
    __shared__ __align__(8) float v_sT[32 * VPAD];    // v transposed [d][j]
    __shared__ float we_s[ED * DD];                   // [c][d]
    __shared__ float agg_s[16 * ED];                  // [r][c]
    __shared__ float inv_s[16], rs_s[16];

    const int t = threadIdx.x;
    const int i0 = blockIdx.x * 16;
    const int h  = blockIdx.y;
    const int d  = t & 31;
    const int r0 = t >> 5;          // 0..7 -> rows r0, r0+8

#pragma unroll
    for (int k = 0; k < 8; k++) {
        const int idx = t + k * 256;                  // c = idx>>5, dd = idx&31
        we_s[idx] = We[(idx >> 5) * INNER + h * DD + (idx & 31)];
    }
#pragma unroll
    for (int k = 0; k < 4; k++) {
        const int idx = t + k * 256;                  // r = idx>>6, c = idx&63
        const int rr = idx >> 6, c = idx & 63;
        float s = 0.f;
#pragma unroll
        for (int qq = 0; qq < 4; qq++)
            s += g_aggu[((size_t)(qq * NROW + i0 + rr) * HH + h) * ED + c];
        agg_s[idx] = s;
    }
    if (t < 16) {
        float s = 0.f;
#pragma unroll
        for (int qq = 0; qq < 4; qq++)
            s += g_sump[qq * (HH * NROW) + h * NROW + i0 + t];
        inv_s[t] = s > 0.f ? 1.f / s : 0.f;
        rs_s[t]  = s > 0.f ? 1.f : 0.f;
    }

    // prefetch chunk 0 into registers (overlaps the staging above)
    float4 ar[2], vr[4];
#pragma unroll
    for (int f = 0; f < 2; f++) {
        const int idx = t + f * 256;                  // row = idx>>5 (0..15)
        ar[f] = *(const float4*)&g_esim[((size_t)h * NROW + i0 + (idx >> 5)) * NROW
                                        + (idx & 31) * 4];
    }
#pragma unroll
    for (int f = 0; f < 4; f++) {
        const int idx = t + f * 256;                  // row = idx>>3 (0..127)
        vr[f] = *(const float4*)&g_v[(size_t)(idx >> 3) * INNER + h * DD + (idx & 7) * 4];
    }
    __syncthreads();

    // edge term (unnormalized)
    float acc[2] = {0.f, 0.f};
#pragma unroll 8
    for (int c = 0; c < ED; c++) {
        const float w = we_s[c * DD + d];
        acc[0] = fmaf(agg_s[r0 * ED + c], w, acc[0]);
        acc[1] = fmaf(agg_s[(r0 + 8) * ED + c], w, acc[1]);
    }

    // v term: 4 chunks of 128 j, register-prefetch pipeline
    ull acc2[2] = {0ull, 0ull};
    for (int ch = 0; ch < 4; ch++) {
        __syncthreads();                              // prev compute done
#pragma unroll
        for (int f = 0; f < 2; f++) {
            const int idx = t + f * 256;
            *(float4*)&a_s[(idx >> 5) * 128 + (idx & 31) * 4] = ar[f];
        }
#pragma unroll
        for (int f = 0; f < 4; f++) {
            const int idx = t + f * 256;
            const int row = idx >> 3, c4 = idx & 7;
            v_sT[(c4 * 4 + 0) * VPAD + row] = vr[f].x;
            v_sT[(c4 * 4 + 1) * VPAD + row] = vr[f].y;
            v_sT[(c4 * 4 + 2) * VPAD + row] = vr[f].z;
            v_sT[(c4 * 4 + 3) * VPAD + row] = vr[f].w;
        }
        __syncthreads();

        if (ch < 3) {                                 // prefetch next chunk
            const int j0n = (ch + 1) * 128;
#pragma unroll
            for (int f = 0; f < 2; f++) {
                const int idx = t + f * 256;
                ar[f] = *(const float4*)&g_esim[((size_t)h * NROW + i0 + (idx >> 5)) * NROW
                                                + j0n + (idx & 31) * 4];
            }
#pragma unroll
            for (int f = 0; f < 4; f++) {
                const int idx = t + f * 256;
                vr[f] = *(const float4*)&g_v[(size_t)(j0n + (idx >> 3)) * INNER
                                             + h * DD + (idx & 7) * 4];
            }
        }

#pragma unroll 8
        for (int jp = 0; jp < 64; jp++) {
            const ull v2 = *(const ull*)&v_sT[d * VPAD + jp * 2];
            acc2[0] = fma2(*(const ull*)&a_s[r0 * 128 + jp * 2], v2, acc2[0]);
            acc2[1] = fma2(*(const ull*)&a_s[(r0 + 8) * 128 + jp * 2], v2, acc2[1]);
        }
    }

    const float bev = be[h * DD + d];
#pragma unroll
    for (int m = 0; m < 2; m++) {
        const int r = r0 + m * 8;
        out[(i0 + r) * INNER + h * DD + d] =
            fmaf(rs_s[r], bev, (acc[m] + hsum2(acc2[m])) * inv_s[r]);
    }
}

// ---------------------------------------------------------------------------
extern "C" void kernel_launch(void* const* d_in, const int* in_sizes, int n_in,
                              void* d_out, int out_size)
{
    const float* nodes = (const float*)d_in[0];
    const float* edges = (const float*)d_in[1];
    const int*   adj   = (const int*)d_in[2];
    const float* Wq    = (const float*)d_in[3];
    const float* bq    = (const float*)d_in[4];
    const float* Wk    = (const float*)d_in[5];
    const float* bk    = (const float*)d_in[6];
    const float* Wv    = (const float*)d_in[7];
    const float* bv    = (const float*)d_in[8];
    const float* We    = (const float*)d_in[9];
    const float* be    = (const float*)d_in[10];
    float* out = (float*)d_out;

    cudaFuncSetAttribute(simagg_kernel,
                         cudaFuncAttributeMaxDynamicSharedMemorySize, QSMEM);

    proj_kernel<<<128, 256>>>(nodes, Wq, bq, Wk, bk, Wv, bv, We, be);
    qk_kernel<<<dim3(16, 16, 8), 256>>>();
    simagg_kernel<<<2048, 256, QSMEM>>>(edges, adj);
    outv_kernel<<<dim3(32, 8), 256>>>(We, be, out);
}

// round 14
// speedup vs baseline: 1.1225x; 1.1225x over previous
#include <cuda_runtime.h>
#include <cstdint>

#define NROW 512
#define HH 8
#define DD 32
#define INNER 256
#define ED 64
#define SCALE 0.17677669529663687f  // 1/sqrt(32)
#define ESTRIDE 68                  // padded row stride (floats), 16B-aligned rows
#define HSMEM (256 * ESTRIDE * 4)   // 69632 B dynamic smem (half row)
#define SPAD 260                    // sim_f row stride (floats), 16B-aligned
#define VPAD 130                    // v_sT row stride (8B-aligned, conflict-free)

// Scratch (device globals; no allocation in kernel_launch).
__device__ float g_q[NROW * INNER];
__device__ float g_k[NROW * INNER];
__device__ float g_v[NROW * INNER];
__device__ float g_t[NROW * HH * ED];        // [i][h][c]  t = We_h^T q_{h,i}
__device__ float g_qbe[NROW * HH];           // q_{h,i} . be_h
__device__ float g_simqk[HH * NROW * NROW];
__device__ float g_esim[HH * NROW * NROW];   // unnormalized exp*adj
__device__ float g_aggu[2 * NROW * HH * ED]; // [half][i][h][c] partial agg
__device__ float g_sump[2 * HH * NROW];      // [half][h][i] partial sums

typedef unsigned long long ull;

__device__ __forceinline__ ull fma2(ull a, ull b, ull c) {
    ull d;
    asm("fma.rn.f32x2 %0, %1, %2, %3;" : "=l"(d) : "l"(a), "l"(b), "l"(c));
    return d;
}
__device__ __forceinline__ ull pack2(float lo, float hi) {
    ull d;
    asm("mov.b64 %0, {%1, %2};" : "=l"(d) : "f"(lo), "f"(hi));
    return d;
}
__device__ __forceinline__ float2 unpack2(ull v) {
    float lo, hi;
    asm("mov.b64 {%0, %1}, %2;" : "=f"(lo), "=f"(hi) : "l"(v));
    return make_float2(lo, hi);
}
__device__ __forceinline__ float hsum2(ull v) {
    float2 f = unpack2(v);
    return f.x + f.y;
}
__device__ __forceinline__ void cp16(unsigned int daddr, const void* gptr) {
    asm volatile("cp.async.cg.shared.global [%0], [%1], 16;\n"
                 :: "r"(daddr), "l"(gptr));
}

// ---------------------------------------------------------------------------
// Kernel A: q/k/v projections + t = We_h^T q + qbe.  4 rows per block.
// ---------------------------------------------------------------------------
__global__ __launch_bounds__(256) void proj_kernel(
    const float* __restrict__ nodes,
    const float* __restrict__ Wq, const float* __restrict__ bq,
    const float* __restrict__ Wk, const float* __restrict__ bk,
    const float* __restrict__ Wv, const float* __restrict__ bv,
    const float* __restrict__ We, const float* __restrict__ be)
{
    __shared__ float node_s[4][128];
    __shared__ float q_s[4][INNER];
    const int t = threadIdx.x;
    const int i0 = blockIdx.x * 4;

    for (int idx = t; idx < 4 * 128; idx += 256)
        node_s[idx >> 7][idx & 127] = nodes[i0 * 128 + idx];
    __syncthreads();

    float aq[4], ak[4], av[4];
    const float bqv = bq[t], bkv = bk[t], bvv = bv[t];
#pragma unroll
    for (int r = 0; r < 4; r++) { aq[r] = bqv; ak[r] = bkv; av[r] = bvv; }

#pragma unroll 8
    for (int k = 0; k < 128; k++) {
        const float wq = Wq[k * INNER + t];
        const float wk = Wk[k * INNER + t];
        const float wv = Wv[k * INNER + t];
#pragma unroll
        for (int r = 0; r < 4; r++) {
            const float nv = node_s[r][k];
            aq[r] = fmaf(nv, wq, aq[r]);
            ak[r] = fmaf(nv, wk, ak[r]);
            av[r] = fmaf(nv, wv, av[r]);
        }
    }
#pragma unroll
    for (int r = 0; r < 4; r++) {
        g_q[(i0 + r) * INNER + t] = aq[r];
        g_k[(i0 + r) * INNER + t] = ak[r];
        g_v[(i0 + r) * INNER + t] = av[r];
        q_s[r][t] = aq[r];
    }
    __syncthreads();

    // t[i][h][c] = sum_d We[c, h*32+d] * q[i, h*32+d]
    for (int idx = t; idx < HH * ED; idx += 256) {
        const int h = idx >> 6, c = idx & 63;
        float acc[4] = {0.f, 0.f, 0.f, 0.f};
        const float* wrow = We + c * INNER + h * DD;
#pragma unroll
        for (int d = 0; d < DD; d++) {
            const float w = wrow[d];
#pragma unroll
            for (int r = 0; r < 4; r++)
                acc[r] = fmaf(w, q_s[r][h * DD + d], acc[r]);
        }
#pragma unroll
        for (int r = 0; r < 4; r++)
            g_t[(i0 + r) * (HH * ED) + idx] = acc[r];
    }

    if (t < 4 * HH) {
        const int r = t >> 3, h = t & 7;
        float s = 0.f;
#pragma unroll
        for (int d = 0; d < DD; d++)
            s = fmaf(q_s[r][h * DD + d], be[h * DD + d], s);
        g_qbe[(i0 + r) * HH + h] = s;
    }
}

// ---------------------------------------------------------------------------
// Kernel QK: simqk[h][i][j] = (q_h[i].k_h[j] + qbe[i][h]) * SCALE
// ---------------------------------------------------------------------------
__global__ __launch_bounds__(256) void qk_kernel()
{
    __shared__ float q_s[32][33];
    __shared__ float k_s[32][33];
    const int t = threadIdx.x;
    const int j0 = blockIdx.x * 32;
    const int i0 = blockIdx.y * 32;
    const int h  = blockIdx.z;

    {
        const int r = t >> 3, c4 = (t & 7) * 4;
        const float4 qv = *(const float4*)&g_q[(i0 + r) * INNER + h * DD + c4];
        q_s[r][c4 + 0] = qv.x; q_s[r][c4 + 1] = qv.y;
        q_s[r][c4 + 2] = qv.z; q_s[r][c4 + 3] = qv.w;
        const float4 kv = *(const float4*)&g_k[(j0 + r) * INNER + h * DD + c4];
        k_s[r][c4 + 0] = kv.x; k_s[r][c4 + 1] = kv.y;
        k_s[r][c4 + 2] = kv.z; k_s[r][c4 + 3] = kv.w;
    }
    __syncthreads();

    const int tx = t & 31, ty = t >> 5;
    float acc[4] = {0.f, 0.f, 0.f, 0.f};
#pragma unroll
    for (int d = 0; d < 32; d++) {
        const float kv = k_s[tx][d];
#pragma unroll
        for (int m = 0; m < 4; m++)
            acc[m] = fmaf(q_s[ty + m * 8][d], kv, acc[m]);
    }
#pragma unroll
    for (int m = 0; m < 4; m++) {
        const int i = i0 + ty + m * 8;
        g_simqk[((size_t)h * NROW + i) * NROW + j0 + tx] =
            (acc[m] + g_qbe[i * HH + h]) * SCALE;
    }
}

// ---------------------------------------------------------------------------
// Probe: empty kernel occupying launch slot 3 so simagg lands in the ncu
// capture window (slot 4). Diagnostic only; ~1 us.
// ---------------------------------------------------------------------------
__global__ void probe_kernel() {}

// ---------------------------------------------------------------------------
// Kernel B: half-row sim + exp + partial sums + partial unnormalized agg.
// grid 1024 = (row i) x (half), 256 threads, occ 2. DMA split into two
// column-groups (c 0..31 then 32..63); pass 1 starts on the first group.
// Pass 2: all 256 threads = (jgroup 0..15, c-quad 0..15), 8 heads in regs.
// ---------------------------------------------------------------------------
__global__ __launch_bounds__(256, 2) void simagg_kernel(
    const float* __restrict__ edges, const int* __restrict__ adj)
{
    extern __shared__ __align__(16) float e_s[];        // [256][ESTRIDE]
    __shared__ __align__(16) float t_s[HH * ESTRIDE];
    __shared__ __align__(16) float sim_f[HH * SPAD];    // [h][j] esim
    __shared__ float wsum[8 * 8];                       // [warp][h]

    const int t = threadIdx.x;
    const int i = blockIdx.x >> 1;
    const int half = blockIdx.x & 1;
    const int jbase = half * 256;

    // ---- DMA: group A = c4 0..7 (floats 0..31), group B = c4 8..15 ----
    {
        const float* gsrc = edges + ((size_t)i * NROW + jbase) * ED;
        unsigned int sbase = (unsigned int)__cvta_generic_to_shared(e_s);
#pragma unroll
        for (int it = 0; it < 8; it++) {
            const int idx = t + it * 256;             // 2048: row=idx>>3, c4=idx&7
            const int row = idx >> 3, c4 = idx & 7;
            cp16(sbase + (unsigned int)(row * ESTRIDE + c4 * 4) * 4,
                 gsrc + (size_t)row * ED + c4 * 4);
        }
        asm volatile("cp.async.commit_group;\n" ::: "memory");
#pragma unroll
        for (int it = 0; it < 8; it++) {
            const int idx = t + it * 256;
            const int row = idx >> 3, c4 = (idx & 7) + 8;
            cp16(sbase + (unsigned int)(row * ESTRIDE + c4 * 4) * 4,
                 gsrc + (size_t)row * ED + c4 * 4);
        }
        asm volatile("cp.async.commit_group;\n" ::: "memory");
    }

    // ---- overlap DMA with staging ----
#pragma unroll
    for (int k = 0; k < 2; k++) {
        const int idx = t + k * 256;
        t_s[(idx >> 6) * ESTRIDE + (idx & 63)] = g_t[i * (HH * ED) + idx];
    }
    const int av = adj[i * NROW + jbase + t];
    float sq[HH];
#pragma unroll
    for (int h = 0; h < HH; h++)
        sq[h] = g_simqk[((size_t)h * NROW + i) * NROW + jbase + t];

    // ---- pass 1: thread = j. Group A = ep[0..7] (floats 0..31), B = ep[8..15] ----
    const int j = t;
    ull acc[HH];
#pragma unroll
    for (int h = 0; h < HH; h++) acc[h] = 0ull;
    const longlong2* ep = (const longlong2*)&e_s[j * ESTRIDE];

    asm volatile("cp.async.wait_group 1;\n" ::: "memory");
    __syncthreads();
    {
        longlong2 er[8];
#pragma unroll
        for (int u = 0; u < 8; u++) er[u] = ep[u];
#pragma unroll
        for (int h = 0; h < HH; h++) {
            const longlong2* tp = (const longlong2*)&t_s[h * ESTRIDE];
            ull a = acc[h];
#pragma unroll
            for (int u = 0; u < 8; u++) {
                const longlong2 tv = tp[u];
                a = fma2((ull)er[u].x, (ull)tv.x, a);
                a = fma2((ull)er[u].y, (ull)tv.y, a);
            }
            acc[h] = a;
        }
    }
    asm volatile("cp.async.wait_group 0;\n" ::: "memory");
    __syncthreads();
    float ex[HH];
    {
        longlong2 er[8];
#pragma unroll
        for (int u = 0; u < 8; u++) er[u] = ep[8 + u];
#pragma unroll
        for (int h = 0; h < HH; h++) {
            const longlong2* tp = (const longlong2*)&t_s[h * ESTRIDE] + 8;
            ull a = acc[h];
#pragma unroll
            for (int u = 0; u < 8; u++) {
                const longlong2 tv = tp[u];
                a = fma2((ull)er[u].x, (ull)tv.x, a);
                a = fma2((ull)er[u].y, (ull)tv.y, a);
            }
            const float simv = fmaf(hsum2(a), SCALE, sq[h]);
            ex[h] = av ? __expf(simv) : 0.f;
        }
    }

    // esim: smem (for pass 2) + gmem (for outv)
#pragma unroll
    for (int h = 0; h < HH; h++) {
        sim_f[h * SPAD + j] = ex[h];
        g_esim[((size_t)h * NROW + i) * NROW + jbase + j] = ex[h];
    }

    // ---- partial sums over j ----
    {
        float s[HH];
#pragma unroll
        for (int h = 0; h < HH; h++) s[h] = ex[h];
#pragma unroll
        for (int o = 16; o > 0; o >>= 1)
#pragma unroll
            for (int h = 0; h < HH; h++)
                s[h] += __shfl_xor_sync(0xffffffffu, s[h], o);
        if ((t & 31) == 0) {
            const int w = t >> 5;
#pragma unroll
            for (int h = 0; h < HH; h++) wsum[w * 8 + h] = s[h];
        }
    }
    __syncthreads();
    if (t < HH) {
        float s = 0.f;
#pragma unroll
        for (int w = 0; w < 8; w++) s += wsum[w * 8 + t];
        g_sump[half * (HH * NROW) + t * NROW + i] = s;
    }

    // ---- pass 2: thread = (jg 0..15, c4 0..15); 16 j per group ----
    ull pa[HH][2];
    const int jg = t >> 4;
    const int c4 = t & 15;
#pragma unroll
    for (int h = 0; h < HH; h++) { pa[h][0] = 0ull; pa[h][1] = 0ull; }
    {
        const int joff = jg * 16;
#pragma unroll
        for (int k4 = 0; k4 < 4; k4++) {
            float4 s4[HH];
#pragma unroll
            for (int h = 0; h < HH; h++)
                s4[h] = *(const float4*)&sim_f[h * SPAD + joff + k4 * 4];
#pragma unroll
            for (int kk = 0; kk < 4; kk++) {
                const int jx = joff + k4 * 4 + kk;
                const longlong2 e2 = *(const longlong2*)&e_s[jx * ESTRIDE + c4 * 4];
#pragma unroll
                for (int h = 0; h < HH; h++) {
                    const float sv = (kk == 0) ? s4[h].x : (kk == 1) ? s4[h].y
                                   : (kk == 2) ? s4[h].z : s4[h].w;
                    const ull sp = pack2(sv, sv);
                    pa[h][0] = fma2(sp, (ull)e2.x, pa[h][0]);
                    pa[h][1] = fma2(sp, (ull)e2.y, pa[h][1]);
                }
            }
        }
    }
    __syncthreads();                 // e_s reads done; alias for partials
    float4* part = (float4*)e_s;     // [jg][h][c4] float4 = 32 KB
#pragma unroll
    for (int h = 0; h < HH; h++) {
        const float2 A = unpack2(pa[h][0]);
        const float2 B = unpack2(pa[h][1]);
        part[(jg * 8 + h) * 16 + c4] = make_float4(A.x, A.y, B.x, B.y);
    }
    __syncthreads();
    if (t < 128) {                   // h = t>>4, c4m = t&15
        const int h = t >> 4;
        const int c4m = t & 15;
        float4 s = part[h * 16 + c4m];
#pragma unroll
        for (int g = 1; g < 16; g++) {
            const float4 p = part[(g * 8 + h) * 16 + c4m];
            s.x += p.x; s.y += p.y; s.z += p.z; s.w += p.w;
        }
        *(float4*)&g_aggu[((size_t)(half * NROW + i) * HH + h) * ED + c4m * 4] = s;
    }
}

// ---------------------------------------------------------------------------
// Kernel C: out = inv * (esim @ v + aggu @ We) + rs * be.
// grid (32 i-tiles of 16, 8 heads) = 256 blocks (2/SM), software-pipelined
// register prefetch of j-chunks. No atomics.
// ---------------------------------------------------------------------------
__global__ __launch_bounds__(256, 2) void outv_kernel(
    const float* __restrict__ We, const float* __restrict__ be,
    float* __restrict__ out)
{
    __shared__ float a_s[16 * 128];                   // esim tile
    __shared__ __align__(8) float v_sT[32 * VPAD];    // v transposed [d][j]
    __shared__ float we_s[ED * DD];                   // [c][d]
    __shared__ float agg_s[16 * ED];                  // [r][c]
    __shared__ float inv_s[16], rs_s[16];

    const int t = threadIdx.x;
    const int i0 = blockIdx.x * 16;
    const int h  = blockIdx.y;
    const int d  = t & 31;
    const int r0 = t >> 5;          // 0..7 -> rows r0, r0+8

#pragma unroll
    for (int k = 0; k < 8; k++) {
        const int idx = t + k * 256;                  // c = idx>>5, dd = idx&31
        we_s[idx] = We[(idx >> 5) * INNER + h * DD + (idx & 31)];
    }
#pragma unroll
    for (int k = 0; k < 4; k++) {
        const int idx = t + k * 256;                  // r = idx>>6, c = idx&63
        const int rr = idx >> 6, c = idx & 63;
        agg_s[idx] = g_aggu[((size_t)(i0 + rr) * HH + h) * ED + c]
                   + g_aggu[((size_t)(NROW + i0 + rr) * HH + h) * ED + c];
    }
    if (t < 16) {
        const float s = g_sump[h * NROW + i0 + t]
                      + g_sump[HH * NROW + h * NROW + i0 + t];
        inv_s[t] = s > 0.f ? 1.f / s : 0.f;
        rs_s[t]  = s > 0.f ? 1.f : 0.f;
    }

    // prefetch chunk 0 into registers (overlaps the staging above)
    float4 ar[2], vr[4];
#pragma unroll
    for (int f = 0; f < 2; f++) {
        const int idx = t + f * 256;                  // row = idx>>5 (0..15)
        ar[f] = *(const float4*)&g_esim[((size_t)h * NROW + i0 + (idx >> 5)) * NROW
                                        + (idx & 31) * 4];
    }
#pragma unroll
    for (int f = 0; f < 4; f++) {
        const int idx = t + f * 256;                  // row = idx>>3 (0..127)
        vr[f] = *(const float4*)&g_v[(size_t)(idx >> 3) * INNER + h * DD + (idx & 7) * 4];
    }
    __syncthreads();

    // edge term (unnormalized)
    float acc[2] = {0.f, 0.f};
#pragma unroll 8
    for (int c = 0; c < ED; c++) {
        const float w = we_s[c * DD + d];
        acc[0] = fmaf(agg_s[r0 * ED + c], w, acc[0]);
        acc[1] = fmaf(agg_s[(r0 + 8) * ED + c], w, acc[1]);
    }

    // v term: 4 chunks of 128 j, register-prefetch pipeline
    ull acc2[2] = {0ull, 0ull};
    for (int ch = 0; ch < 4; ch++) {
        __syncthreads();                              // prev compute done
#pragma unroll
        for (int f = 0; f < 2; f++) {
            const int idx = t + f * 256;
            *(float4*)&a_s[(idx >> 5) * 128 + (idx & 31) * 4] = ar[f];
        }
#pragma unroll
        for (int f = 0; f < 4; f++) {
            const int idx = t + f * 256;
            const int row = idx >> 3, c4 = idx & 7;
            v_sT[(c4 * 4 + 0) * VPAD + row] = vr[f].x;
            v_sT[(c4 * 4 + 1) * VPAD + row] = vr[f].y;
            v_sT[(c4 * 4 + 2) * VPAD + row] = vr[f].z;
            v_sT[(c4 * 4 + 3) * VPAD + row] = vr[f].w;
        }
        __syncthreads();

        if (ch < 3) {                                 // prefetch next chunk
            const int j0n = (ch + 1) * 128;
#pragma unroll
            for (int f = 0; f < 2; f++) {
                const int idx = t + f * 256;
                ar[f] = *(const float4*)&g_esim[((size_t)h * NROW + i0 + (idx >> 5)) * NROW
                                                + j0n + (idx & 31) * 4];
            }
#pragma unroll
            for (int f = 0; f < 4; f++) {
                const int idx = t + f * 256;
                vr[f] = *(const float4*)&g_v[(size_t)(j0n + (idx >> 3)) * INNER
                                             + h * DD + (idx & 7) * 4];
            }
        }

#pragma unroll 8
        for (int jp = 0; jp < 64; jp++) {
            const ull v2 = *(const ull*)&v_sT[d * VPAD + jp * 2];
            acc2[0] = fma2(*(const ull*)&a_s[r0 * 128 + jp * 2], v2, acc2[0]);
            acc2[1] = fma2(*(const ull*)&a_s[(r0 + 8) * 128 + jp * 2], v2, acc2[1]);
        }
    }

    const float bev = be[h * DD + d];
#pragma unroll
    for (int m = 0; m < 2; m++) {
        const int r = r0 + m * 8;
        out[(i0 + r) * INNER + h * DD + d] =
            fmaf(rs_s[r], bev, (acc[m] + hsum2(acc2[m])) * inv_s[r]);
    }
}

// ---------------------------------------------------------------------------
extern "C" void kernel_launch(void* const* d_in, const int* in_sizes, int n_in,
                              void* d_out, int out_size)
{
    const float* nodes = (const float*)d_in[0];
    const float* edges = (const float*)d_in[1];
    const int*   adj   = (const int*)d_in[2];
    const float* Wq    = (const float*)d_in[3];
    const float* bq    = (const float*)d_in[4];
    const float* Wk    = (const float*)d_in[5];
    const float* bk    = (const float*)d_in[6];
    const float* Wv    = (const float*)d_in[7];
    const float* bv    = (const float*)d_in[8];
    const float* We    = (const float*)d_in[9];
    const float* be    = (const float*)d_in[10];
    float* out = (float*)d_out;

    cudaFuncSetAttribute(simagg_kernel,
                         cudaFuncAttributeMaxDynamicSharedMemorySize, HSMEM);

    proj_kernel<<<128, 256>>>(nodes, Wq, bq, Wk, bk, Wv, bv, We, be);
    qk_kernel<<<dim3(16, 16, 8), 256>>>();
    probe_kernel<<<1, 32>>>();     // occupies profiled slot 3 -> simagg is slot 4
    simagg_kernel<<<1024, 256, HSMEM>>>(edges, adj);
    outv_kernel<<<dim3(32, 8), 256>>>(We, be, out);
}

// round 15
// speedup vs baseline: 1.1372x; 1.0131x over previous
#include <cuda_runtime.h>
#include <cstdint>

#define NROW 512
#define HH 8
#define DD 32
#define INNER 256
#define ED 64
#define SCALE 0.17677669529663687f  // 1/sqrt(32)
#define ESTRIDE 68                  // padded stride for non-simagg uses
#define ESW 64                      // simagg edge tile stride (swizzled)
#define SIMAGG_DSMEM (256 * ESW * 4)  // 65536 B dynamic
#define SPAD 260                    // sim_f row stride (floats), 16B-aligned
#define VPAD 130                    // v_sT row stride (8B-aligned, conflict-free)

// Scratch (device globals; no allocation in kernel_launch).
__device__ float g_q[NROW * INNER];
__device__ float g_k[NROW * INNER];
__device__ float g_v[NROW * INNER];
__device__ float g_t[NROW * HH * ED];        // [i][h][c]  t = We_h^T q_{h,i}
__device__ float g_qbe[NROW * HH];           // q_{h,i} . be_h
__device__ float g_simqk[HH * NROW * NROW];
__device__ float g_esim[HH * NROW * NROW];   // unnormalized exp*adj
__device__ float g_aggu[2 * NROW * HH * ED]; // [half][i][h][c] partial agg
__device__ float g_sump[2 * HH * NROW];      // [half][h][i] partial sums

typedef unsigned long long ull;

__device__ __forceinline__ ull fma2(ull a, ull b, ull c) {
    ull d;
    asm("fma.rn.f32x2 %0, %1, %2, %3;" : "=l"(d) : "l"(a), "l"(b), "l"(c));
    return d;
}
__device__ __forceinline__ ull pack2(float lo, float hi) {
    ull d;
    asm("mov.b64 %0, {%1, %2};" : "=l"(d) : "f"(lo), "f"(hi));
    return d;
}
__device__ __forceinline__ float2 unpack2(ull v) {
    float lo, hi;
    asm("mov.b64 {%0, %1}, %2;" : "=f"(lo), "=f"(hi) : "l"(v));
    return make_float2(lo, hi);
}
__device__ __forceinline__ float hsum2(ull v) {
    float2 f = unpack2(v);
    return f.x + f.y;
}
__device__ __forceinline__ void cp16(unsigned int daddr, const void* gptr) {
    asm volatile("cp.async.cg.shared.global [%0], [%1], 16;\n"
                 :: "r"(daddr), "l"(gptr));
}

// ---------------------------------------------------------------------------
// Kernel A: q/k/v projections + t = We_h^T q + qbe.  4 rows per block.
// ---------------------------------------------------------------------------
__global__ __launch_bounds__(256) void proj_kernel(
    const float* __restrict__ nodes,
    const float* __restrict__ Wq, const float* __restrict__ bq,
    const float* __restrict__ Wk, const float* __restrict__ bk,
    const float* __restrict__ Wv, const float* __restrict__ bv,
    const float* __restrict__ We, const float* __restrict__ be)
{
    __shared__ float node_s[4][128];
    __shared__ float q_s[4][INNER];
    const int t = threadIdx.x;
    const int i0 = blockIdx.x * 4;

    for (int idx = t; idx < 4 * 128; idx += 256)
        node_s[idx >> 7][idx & 127] = nodes[i0 * 128 + idx];
    __syncthreads();

    float aq[4], ak[4], av[4];
    const float bqv = bq[t], bkv = bk[t], bvv = bv[t];
#pragma unroll
    for (int r = 0; r < 4; r++) { aq[r] = bqv; ak[r] = bkv; av[r] = bvv; }

#pragma unroll 8
    for (int k = 0; k < 128; k++) {
        const float wq = Wq[k * INNER + t];
        const float wk = Wk[k * INNER + t];
        const float wv = Wv[k * INNER + t];
#pragma unroll
        for (int r = 0; r < 4; r++) {
            const float nv = node_s[r][k];
            aq[r] = fmaf(nv, wq, aq[r]);
            ak[r] = fmaf(nv, wk, ak[r]);
            av[r] = fmaf(nv, wv, av[r]);
        }
    }
#pragma unroll
    for (int r = 0; r < 4; r++) {
        g_q[(i0 + r) * INNER + t] = aq[r];
        g_k[(i0 + r) * INNER + t] = ak[r];
        g_v[(i0 + r) * INNER + t] = av[r];
        q_s[r][t] = aq[r];
    }
    __syncthreads();

    // t[i][h][c] = sum_d We[c, h*32+d] * q[i, h*32+d]
    for (int idx = t; idx < HH * ED; idx += 256) {
        const int h = idx >> 6, c = idx & 63;
        float acc[4] = {0.f, 0.f, 0.f, 0.f};
        const float* wrow = We + c * INNER + h * DD;
#pragma unroll
        for (int d = 0; d < DD; d++) {
            const float w = wrow[d];
#pragma unroll
            for (int r = 0; r < 4; r++)
                acc[r] = fmaf(w, q_s[r][h * DD + d], acc[r]);
        }
#pragma unroll
        for (int r = 0; r < 4; r++)
            g_t[(i0 + r) * (HH * ED) + idx] = acc[r];
    }

    if (t < 4 * HH) {
        const int r = t >> 3, h = t & 7;
        float s = 0.f;
#pragma unroll
        for (int d = 0; d < DD; d++)
            s = fmaf(q_s[r][h * DD + d], be[h * DD + d], s);
        g_qbe[(i0 + r) * HH + h] = s;
    }
}

// ---------------------------------------------------------------------------
// Kernel QK: simqk[h][i][j] = (q_h[i].k_h[j] + qbe[i][h]) * SCALE
// ---------------------------------------------------------------------------
__global__ __launch_bounds__(256) void qk_kernel()
{
    __shared__ float q_s[32][33];
    __shared__ float k_s[32][33];
    const int t = threadIdx.x;
    const int j0 = blockIdx.x * 32;
    const int i0 = blockIdx.y * 32;
    const int h  = blockIdx.z;

    {
        const int r = t >> 3, c4 = (t & 7) * 4;
        const float4 qv = *(const float4*)&g_q[(i0 + r) * INNER + h * DD + c4];
        q_s[r][c4 + 0] = qv.x; q_s[r][c4 + 1] = qv.y;
        q_s[r][c4 + 2] = qv.z; q_s[r][c4 + 3] = qv.w;
        const float4 kv = *(const float4*)&g_k[(j0 + r) * INNER + h * DD + c4];
        k_s[r][c4 + 0] = kv.x; k_s[r][c4 + 1] = kv.y;
        k_s[r][c4 + 2] = kv.z; k_s[r][c4 + 3] = kv.w;
    }
    __syncthreads();

    const int tx = t & 31, ty = t >> 5;
    float acc[4] = {0.f, 0.f, 0.f, 0.f};
#pragma unroll
    for (int d = 0; d < 32; d++) {
        const float kv = k_s[tx][d];
#pragma unroll
        for (int m = 0; m < 4; m++)
            acc[m] = fmaf(q_s[ty + m * 8][d], kv, acc[m]);
    }
#pragma unroll
    for (int m = 0; m < 4; m++) {
        const int i = i0 + ty + m * 8;
        g_simqk[((size_t)h * NROW + i) * NROW + j0 + tx] =
            (acc[m] + g_qbe[i * HH + h]) * SCALE;
    }
}

// ---------------------------------------------------------------------------
// Probe: keeps simagg in the profiled slot (diagnostic; ~2.5 us).
// ---------------------------------------------------------------------------
__global__ void probe_kernel() {}

// ---------------------------------------------------------------------------
// Kernel B: half-row sim + exp + partial sums + partial unnormalized agg.
// grid 1024, 256 threads, occupancy 3 (64 KB swizzled edge tile, ~80 regs).
// Edge tile: stride 64 floats, 16B slot swizzle  slot = c4 ^ (row & 7).
// ---------------------------------------------------------------------------
__global__ __launch_bounds__(256, 3) void simagg_kernel(
    const float* __restrict__ edges, const int* __restrict__ adj)
{
    extern __shared__ __align__(16) float e_s[];        // [256][ESW] swizzled
    __shared__ __align__(16) float t_s[HH * ESW];
    __shared__ float sim_f[HH * 256];                   // [h][j] esim
    __shared__ float wsum[8 * 8];                       // [warp][h]

    const int t = threadIdx.x;
    const int i = blockIdx.x >> 1;
    const int half = blockIdx.x & 1;
    const int jbase = half * 256;

    // ---- DMA: group A = columns 0..31 (c4 0..7), group B = 32..63 ----
    {
        const float* gsrc = edges + ((size_t)i * NROW + jbase) * ED;
        unsigned int sbase = (unsigned int)__cvta_generic_to_shared(e_s);
#pragma unroll
        for (int it = 0; it < 8; it++) {
            const int idx = t + it * 256;             // row = idx>>3, c4 = idx&7
            const int row = idx >> 3, c4 = idx & 7;
            const int slot = c4 ^ (row & 7);
            cp16(sbase + (unsigned int)(row * ESW + slot * 4) * 4,
                 gsrc + (size_t)row * ED + c4 * 4);
        }
        asm volatile("cp.async.commit_group;\n" ::: "memory");
#pragma unroll
        for (int it = 0; it < 8; it++) {
            const int idx = t + it * 256;
            const int row = idx >> 3, c4 = (idx & 7) + 8;
            const int slot = c4 ^ (row & 7);          // stays in 8..15
            cp16(sbase + (unsigned int)(row * ESW + slot * 4) * 4,
                 gsrc + (size_t)row * ED + c4 * 4);
        }
        asm volatile("cp.async.commit_group;\n" ::: "memory");
    }

    // ---- overlap DMA with staging ----
#pragma unroll
    for (int k = 0; k < 2; k++) {
        const int idx = t + k * 256;
        t_s[(idx >> 6) * ESW + (idx & 63)] = g_t[i * (HH * ED) + idx];
    }
    const int av = adj[i * NROW + jbase + t];
    float sq[HH];
#pragma unroll
    for (int h = 0; h < HH; h++)
        sq[h] = g_simqk[((size_t)h * NROW + i) * NROW + jbase + t];

    // ---- pass 1: thread = j; column-order traversal (slot = u ^ s) ----
    const int j = t;
    const int s = j & 7;
    ull acc[HH];
#pragma unroll
    for (int h = 0; h < HH; h++) acc[h] = 0ull;

    asm volatile("cp.async.wait_group 1;\n" ::: "memory");
    __syncthreads();
    {   // columns 0..31: c4 units u = 0..7
#pragma unroll
        for (int ug = 0; ug < 2; ug++) {
            longlong2 er[4];
#pragma unroll
            for (int v = 0; v < 4; v++) {
                const int u = ug * 4 + v;
                er[v] = *(const longlong2*)&e_s[j * ESW + (u ^ s) * 4];
            }
#pragma unroll
            for (int h = 0; h < HH; h++) {
                ull a = acc[h];
#pragma unroll
                for (int v = 0; v < 4; v++) {
                    const int u = ug * 4 + v;
                    const longlong2 tv = *(const longlong2*)&t_s[h * ESW + u * 4];
                    a = fma2((ull)er[v].x, (ull)tv.x, a);
                    a = fma2((ull)er[v].y, (ull)tv.y, a);
                }
                acc[h] = a;
            }
        }
    }
    asm volatile("cp.async.wait_group 0;\n" ::: "memory");
    __syncthreads();
    float ex[HH];
    {   // columns 32..63: u = 8..15 (slot = u ^ s stays in 8..15)
#pragma unroll
        for (int ug = 0; ug < 2; ug++) {
            longlong2 er[4];
#pragma unroll
            for (int v = 0; v < 4; v++) {
                const int u = 8 + ug * 4 + v;
                er[v] = *(const longlong2*)&e_s[j * ESW + (u ^ s) * 4];
            }
#pragma unroll
            for (int h = 0; h < HH; h++) {
                ull a = acc[h];
#pragma unroll
                for (int v = 0; v < 4; v++) {
                    const int u = 8 + ug * 4 + v;
                    const longlong2 tv = *(const longlong2*)&t_s[h * ESW + u * 4];
                    a = fma2((ull)er[v].x, (ull)tv.x, a);
                    a = fma2((ull)er[v].y, (ull)tv.y, a);
                }
                acc[h] = a;
            }
        }
#pragma unroll
        for (int h = 0; h < HH; h++) {
            const float simv = fmaf(hsum2(acc[h]), SCALE, sq[h]);
            ex[h] = av ? __expf(simv) : 0.f;
        }
    }

    // esim: smem (for pass 2) + gmem (for outv)
#pragma unroll
    for (int h = 0; h < HH; h++) {
        sim_f[h * 256 + j] = ex[h];
        g_esim[((size_t)h * NROW + i) * NROW + jbase + j] = ex[h];
    }

    // ---- partial sums over j ----
    {
        float sred[HH];
#pragma unroll
        for (int h = 0; h < HH; h++) sred[h] = ex[h];
#pragma unroll
        for (int o = 16; o > 0; o >>= 1)
#pragma unroll
            for (int h = 0; h < HH; h++)
                sred[h] += __shfl_xor_sync(0xffffffffu, sred[h], o);
        if ((t & 31) == 0) {
            const int w = t >> 5;
#pragma unroll
            for (int h = 0; h < HH; h++) wsum[w * 8 + h] = sred[h];
        }
    }
    __syncthreads();
    if (t < HH) {
        float sr = 0.f;
#pragma unroll
        for (int w = 0; w < 8; w++) sr += wsum[w * 8 + t];
        g_sump[half * (HH * NROW) + t * NROW + i] = sr;
    }

    // ---- pass 2: thread = (jg 0..15, c4 0..15); scalar sim broadcasts ----
    ull pa[HH][2];
    const int jg = t >> 4;
    const int c4 = t & 15;
#pragma unroll
    for (int h = 0; h < HH; h++) { pa[h][0] = 0ull; pa[h][1] = 0ull; }
    {
        const int joff = jg * 16;
#pragma unroll 4
        for (int jj = 0; jj < 16; jj++) {
            const int jx = joff + jj;
            const longlong2 e2 =
                *(const longlong2*)&e_s[jx * ESW + (c4 ^ (jx & 7)) * 4];
#pragma unroll
            for (int h = 0; h < HH; h++) {
                const float sv = sim_f[h * 256 + jx];
                const ull sp = pack2(sv, sv);
                pa[h][0] = fma2(sp, (ull)e2.x, pa[h][0]);
                pa[h][1] = fma2(sp, (ull)e2.y, pa[h][1]);
            }
        }
    }
    // NOTE: c4 ^ (jx & 7): for c4 >= 8 the slot stays in 8..15, for c4 < 8 in
    // 0..7 — matches the storage swizzle, giving edge column c4 of row jx.
    __syncthreads();                 // e_s reads done; alias for partials
    float4* part = (float4*)e_s;     // [jg][h][c4] float4 = 32 KB
#pragma unroll
    for (int h = 0; h < HH; h++) {
        const float2 A = unpack2(pa[h][0]);
        const float2 B = unpack2(pa[h][1]);
        part[(jg * 8 + h) * 16 + c4] = make_float4(A.x, A.y, B.x, B.y);
    }
    __syncthreads();
    if (t < 128) {                   // h = t>>4, c4m = t&15
        const int h = t >> 4;
        const int c4m = t & 15;
        float4 sv = part[h * 16 + c4m];
#pragma unroll
        for (int g = 1; g < 16; g++) {
            const float4 p = part[(g * 8 + h) * 16 + c4m];
            sv.x += p.x; sv.y += p.y; sv.z += p.z; sv.w += p.w;
        }
        *(float4*)&g_aggu[((size_t)(half * NROW + i) * HH + h) * ED + c4m * 4] = sv;
    }
}

// ---------------------------------------------------------------------------
// Kernel C: out = inv * (esim @ v + aggu @ We) + rs * be.
// grid (32 i-tiles of 16, 8 heads) = 256 blocks (2/SM), software-pipelined
// register prefetch of j-chunks. No atomics.
// ---------------------------------------------------------------------------
__global__ __launch_bounds__(256, 2) void outv_kernel(
    const float* __restrict__ We, const float* __restrict__ be,
    float* __restrict__ out)
{
    __shared__ float a_s[16 * 128];                   // esim tile
    __shared__ __align__(8) float v_sT[32 * VPAD];    // v transposed [d][j]
    __shared__ float we_s[ED * DD];                   // [c][d]
    __shared__ float agg_s[16 * ED];                  // [r][c]
    __shared__ float inv_s[16], rs_s[16];

    const int t = threadIdx.x;
    const int i0 = blockIdx.x * 16;
    const int h  = blockIdx.y;
    const int d  = t & 31;
    const int r0 = t >> 5;          // 0..7 -> rows r0, r0+8

#pragma unroll
    for (int k = 0; k < 8; k++) {
        const int idx = t + k * 256;                  // c = idx>>5, dd = idx&31
        we_s[idx] = We[(idx >> 5) * INNER + h * DD + (idx & 31)];
    }
#pragma unroll
    for (int k = 0; k < 4; k++) {
        const int idx = t + k * 256;                  // r = idx>>6, c = idx&63
        const int rr = idx >> 6, c = idx & 63;
        agg_s[idx] = g_aggu[((size_t)(i0 + rr) * HH + h) * ED + c]
                   + g_aggu[((size_t)(NROW + i0 + rr) * HH + h) * ED + c];
    }
    if (t < 16) {
        const float s = g_sump[h * NROW + i0 + t]
                      + g_sump[HH * NROW + h * NROW + i0 + t];
        inv_s[t] = s > 0.f ? 1.f / s : 0.f;
        rs_s[t]  = s > 0.f ? 1.f : 0.f;
    }

    // prefetch chunk 0 into registers (overlaps the staging above)
    float4 ar[2], vr[4];
#pragma unroll
    for (int f = 0; f < 2; f++) {
        const int idx = t + f * 256;                  // row = idx>>5 (0..15)
        ar[f] = *(const float4*)&g_esim[((size_t)h * NROW + i0 + (idx >> 5)) * NROW
                                        + (idx & 31) * 4];
    }
#pragma unroll
    for (int f = 0; f < 4; f++) {
        const int idx = t + f * 256;                  // row = idx>>3 (0..127)
        vr[f] = *(const float4*)&g_v[(size_t)(idx >> 3) * INNER + h * DD + (idx & 7) * 4];
    }
    __syncthreads();

    // edge term (unnormalized)
    float acc[2] = {0.f, 0.f};
#pragma unroll 8
    for (int c = 0; c < ED; c++) {
        const float w = we_s[c * DD + d];
        acc[0] = fmaf(agg_s[r0 * ED + c], w, acc[0]);
        acc[1] = fmaf(agg_s[(r0 + 8) * ED + c], w, acc[1]);
    }

    // v term: 4 chunks of 128 j, register-prefetch pipeline
    ull acc2[2] = {0ull, 0ull};
    for (int ch = 0; ch < 4; ch++) {
        __syncthreads();                              // prev compute done
#pragma unroll
        for (int f = 0; f < 2; f++) {
            const int idx = t + f * 256;
            *(float4*)&a_s[(idx >> 5) * 128 + (idx & 31) * 4] = ar[f];
        }
#pragma unroll
        for (int f = 0; f < 4; f++) {
            const int idx = t + f * 256;
            const int row = idx >> 3, c4 = idx & 7;
            v_sT[(c4 * 4 + 0) * VPAD + row] = vr[f].x;
            v_sT[(c4 * 4 + 1) * VPAD + row] = vr[f].y;
            v_sT[(c4 * 4 + 2) * VPAD + row] = vr[f].z;
            v_sT[(c4 * 4 + 3) * VPAD + row] = vr[f].w;
        }
        __syncthreads();

        if (ch < 3) {                                 // prefetch next chunk
            const int j0n = (ch + 1) * 128;
#pragma unroll
            for (int f = 0; f < 2; f++) {
                const int idx = t + f * 256;
                ar[f] = *(const float4*)&g_esim[((size_t)h * NROW + i0 + (idx >> 5)) * NROW
                                                + j0n + (idx & 31) * 4];
            }
#pragma unroll
            for (int f = 0; f < 4; f++) {
                const int idx = t + f * 256;
                vr[f] = *(const float4*)&g_v[(size_t)(j0n + (idx >> 3)) * INNER
                                             + h * DD + (idx & 7) * 4];
            }
        }

#pragma unroll 8
        for (int jp = 0; jp < 64; jp++) {
            const ull v2 = *(const ull*)&v_sT[d * VPAD + jp * 2];
            acc2[0] = fma2(*(const ull*)&a_s[r0 * 128 + jp * 2], v2, acc2[0]);
            acc2[1] = fma2(*(const ull*)&a_s[(r0 + 8) * 128 + jp * 2], v2, acc2[1]);
        }
    }

    const float bev = be[h * DD + d];
#pragma unroll
    for (int m = 0; m < 2; m++) {
        const int r = r0 + m * 8;
        out[(i0 + r) * INNER + h * DD + d] =
            fmaf(rs_s[r], bev, (acc[m] + hsum2(acc2[m])) * inv_s[r]);
    }
}

// ---------------------------------------------------------------------------
extern "C" void kernel_launch(void* const* d_in, const int* in_sizes, int n_in,
                              void* d_out, int out_size)
{
    const float* nodes = (const float*)d_in[0];
    const float* edges = (const float*)d_in[1];
    const int*   adj   = (const int*)d_in[2];
    const float* Wq    = (const float*)d_in[3];
    const float* bq    = (const float*)d_in[4];
    const float* Wk    = (const float*)d_in[5];
    const float* bk    = (const float*)d_in[6];
    const float* Wv    = (const float*)d_in[7];
    const float* bv    = (const float*)d_in[8];
    const float* We    = (const float*)d_in[9];
    const float* be    = (const float*)d_in[10];
    float* out = (float*)d_out;

    cudaFuncSetAttribute(simagg_kernel,
                         cudaFuncAttributeMaxDynamicSharedMemorySize, SIMAGG_DSMEM);

    proj_kernel<<<128, 256>>>(nodes, Wq, bq, Wk, bk, Wv, bv, We, be);
    qk_kernel<<<dim3(16, 16, 8), 256>>>();
    probe_kernel<<<1, 32>>>();     // keeps simagg in the profiled slot
    simagg_kernel<<<1024, 256, SIMAGG_DSMEM>>>(edges, adj);
    outv_kernel<<<dim3(32, 8), 256>>>(We, be, out);
}